// round 3
// baseline (speedup 1.0000x reference)
#include <cuda_runtime.h>
#include <cuda_bf16.h>
#include <math.h>

#define V_SZ 2048
#define L_SZ 16
#define H_SZ 8
#define D_SZ 64
#define B_SZ 8192
#define NW_TOTAL 8192
#define N_NAMES 2048
#define TEMP_INV 0.125f
#define SMPAD 68

// -------- scratch (static device allocations are allowed) --------
__device__ float g_cq[V_SZ * H_SZ * D_SZ];
__device__ float g_ck[V_SZ * H_SZ * D_SZ];
__device__ float g_cv[V_SZ * H_SZ * D_SZ];
__device__ float g_pq[L_SZ * H_SZ * D_SZ];
__device__ float g_pk[L_SZ * H_SZ * D_SZ];
__device__ float g_pv[L_SZ * H_SZ * D_SZ];
__device__ float g_pooled[B_SZ * H_SZ * D_SZ];   // (B,H,D)
__device__ float g_xflat[B_SZ * 512];            // (B, D*8)
__device__ int   g_segoff[N_NAMES];

// -------- K0: pos embedding -> pq/pk/pv  (grid 16, block 256) --------
__global__ void qkv_pos_kernel(const float* __restrict__ Wp, const float* __restrict__ bp) {
    int l = blockIdx.x;
    __shared__ float sp[64];
    int tid = threadIdx.x;
    if (tid < 64) {
        int f = tid & 31;
        double inv = pow(10000.0, -(double)f / 32.0);
        double ph = (double)l * inv;
        sp[tid] = (float)((tid < 32) ? cos(ph) : sin(ph));
    }
    __syncthreads();
    for (int c = tid; c < 1536; c += 256) {
        float a = 0.f;
        #pragma unroll 8
        for (int k = 0; k < 64; k++) a += sp[k] * Wp[k * 1536 + c];
        a += bp[c];
        int t = c >> 9, rem = c & 511;
        float* dst = (t == 0) ? g_pq : (t == 1) ? g_pk : g_pv;
        dst[l * 512 + rem] = a;
    }
}

// -------- K1: char_emb @ Wc + bc -> cq/ck/cv  (grid 256, block 256) --------
__global__ __launch_bounds__(256) void qkv_char_kernel(
    const float* __restrict__ emb, const float* __restrict__ Wc, const float* __restrict__ bc) {
    int row0 = blockIdx.x * 8;
    __shared__ float se[8][64];
    int tid = threadIdx.x;
    for (int idx = tid; idx < 512; idx += 256)
        se[idx >> 6][idx & 63] = emb[(row0 + (idx >> 6)) * 64 + (idx & 63)];
    __syncthreads();
    float acc[6][8];
    #pragma unroll
    for (int c = 0; c < 6; c++)
        #pragma unroll
        for (int r = 0; r < 8; r++) acc[c][r] = 0.f;
    for (int k = 0; k < 64; k++) {
        float w[6];
        #pragma unroll
        for (int c = 0; c < 6; c++) w[c] = Wc[k * 1536 + tid + c * 256];
        #pragma unroll
        for (int r = 0; r < 8; r++) {
            float e = se[r][k];
            #pragma unroll
            for (int c = 0; c < 6; c++) acc[c][r] = fmaf(e, w[c], acc[c][r]);
        }
    }
    #pragma unroll
    for (int c = 0; c < 6; c++) {
        int col = tid + c * 256;
        float bias = bc[col];
        int t = col >> 9, rem = col & 511;
        float* dst = (t == 0) ? g_cq : (t == 1) ? g_ck : g_cv;
        #pragma unroll
        for (int r = 0; r < 8; r++) dst[(row0 + r) * 512 + rem] = acc[c][r] + bias;
    }
}

// -------- K_scan: exclusive prefix of n_words (1 block, 256 threads) --------
__global__ void seg_scan_kernel(const int* __restrict__ nw) {
    __shared__ int s[N_NAMES];
    __shared__ int csum[32];
    int tid = threadIdx.x;
    for (int i = tid; i < N_NAMES; i += 256) s[i] = nw[i];
    __syncthreads();
    if (tid < 32) {
        int a = 0;
        for (int k = 0; k < 64; k++) a += s[tid * 64 + k];
        int x = a;
        #pragma unroll
        for (int o = 1; o < 32; o <<= 1) {
            int y = __shfl_up_sync(0xffffffff, x, o);
            if (tid >= o) x += y;
        }
        csum[tid] = x - a;  // exclusive chunk offset
    }
    __syncthreads();
    if (tid < 32) {
        int off = csum[tid];
        for (int k = 0; k < 64; k++) {
            g_segoff[tid * 64 + k] = off;
            off += s[tid * 64 + k];
        }
    }
}

// -------- K2: attention + LN + masked pool. One block per (b,h). --------
__global__ __launch_bounds__(128) void attn_kernel(
    const int* __restrict__ code_g, const float* __restrict__ gamma, const float* __restrict__ beta) {
    __shared__ float sCQ[16][SMPAD], sCK[16][SMPAD], sPQ[16][SMPAD], sPK[16][SMPAD];
    __shared__ float sV[16][SMPAD], sO[16][SMPAD];
    __shared__ float S[16][17];
    __shared__ int code[16];
    __shared__ float sinv[16], smu[16], srstd[16];

    int tid = threadIdx.x;
    int b = blockIdx.x >> 3;
    int h = blockIdx.x & 7;

    if (tid < 16) code[tid] = code_g[b * 16 + tid];
    __syncthreads();

    // Gather per-position q/k/v rows (L2-resident tables)
    for (int idx = tid; idx < 1024; idx += 128) {
        int p = idx >> 6, d = idx & 63;
        int cb = code[p] * 512 + h * 64 + d;
        int pb = p * 512 + h * 64 + d;
        sCQ[p][d] = g_cq[cb];
        sCK[p][d] = g_ck[cb];
        sPQ[p][d] = g_pq[pb];
        sPK[p][d] = g_pk[pb];
        sV[p][d]  = g_cv[cb] + g_pv[pb];
    }
    __syncthreads();

    // Scores: S[i][j] = cq_i·(ck_j+pk_j) + pq_i·pk_j + pq_j·ck_i, scaled 1/8
    if (tid < 64) {
        int it = tid >> 3, jt = tid & 7;  // tiles {it, it+8} x {jt, jt+8}
        float a00 = 0.f, a01 = 0.f, a10 = 0.f, a11 = 0.f;
        #pragma unroll 4
        for (int d = 0; d < 64; d += 4) {
            float4 cqi0 = *(const float4*)&sCQ[it][d];
            float4 cqi1 = *(const float4*)&sCQ[it + 8][d];
            float4 pqi0 = *(const float4*)&sPQ[it][d];
            float4 pqi1 = *(const float4*)&sPQ[it + 8][d];
            float4 cki0 = *(const float4*)&sCK[it][d];
            float4 cki1 = *(const float4*)&sCK[it + 8][d];
            float4 ckj0 = *(const float4*)&sCK[jt][d];
            float4 ckj1 = *(const float4*)&sCK[jt + 8][d];
            float4 pkj0 = *(const float4*)&sPK[jt][d];
            float4 pkj1 = *(const float4*)&sPK[jt + 8][d];
            float4 pqj0 = *(const float4*)&sPQ[jt][d];
            float4 pqj1 = *(const float4*)&sPQ[jt + 8][d];
            float4 kc0, kc1;
            kc0.x = ckj0.x + pkj0.x; kc0.y = ckj0.y + pkj0.y; kc0.z = ckj0.z + pkj0.z; kc0.w = ckj0.w + pkj0.w;
            kc1.x = ckj1.x + pkj1.x; kc1.y = ckj1.y + pkj1.y; kc1.z = ckj1.z + pkj1.z; kc1.w = ckj1.w + pkj1.w;
#define ACC4(acc, cqi, pqi, cki, kcj, pkj, pqj)                              \
            acc += cqi.x * kcj.x + cqi.y * kcj.y + cqi.z * kcj.z + cqi.w * kcj.w \
                 + pqi.x * pkj.x + pqi.y * pkj.y + pqi.z * pkj.z + pqi.w * pkj.w \
                 + pqj.x * cki.x + pqj.y * cki.y + pqj.z * cki.z + pqj.w * cki.w;
            ACC4(a00, cqi0, pqi0, cki0, kc0, pkj0, pqj0)
            ACC4(a01, cqi0, pqi0, cki0, kc1, pkj1, pqj1)
            ACC4(a10, cqi1, pqi1, cki1, kc0, pkj0, pqj0)
            ACC4(a11, cqi1, pqi1, cki1, kc1, pkj1, pqj1)
#undef ACC4
        }
        bool m0 = (code[jt] == 0), m1 = (code[jt + 8] == 0);
        S[it][jt]          = m0 ? -1e9f : a00 * TEMP_INV;
        S[it][jt + 8]      = m1 ? -1e9f : a01 * TEMP_INV;
        S[it + 8][jt]      = m0 ? -1e9f : a10 * TEMP_INV;
        S[it + 8][jt + 8]  = m1 ? -1e9f : a11 * TEMP_INV;
    }
    __syncthreads();

    // Softmax per row
    if (tid < 16) {
        float m = -1e30f;
        #pragma unroll
        for (int j = 0; j < 16; j++) m = fmaxf(m, S[tid][j]);
        float sum = 0.f;
        #pragma unroll
        for (int j = 0; j < 16; j++) {
            float e = expf(S[tid][j] - m);
            S[tid][j] = e;
            sum += e;
        }
        sinv[tid] = 1.f / sum;
    }
    __syncthreads();

    // out = P @ V ; thread handles (i, 8 d's)
    {
        int i = tid >> 3;
        int d0 = (tid & 7) * 8;
        float4 acc0 = make_float4(0.f, 0.f, 0.f, 0.f);
        float4 acc1 = make_float4(0.f, 0.f, 0.f, 0.f);
        #pragma unroll
        for (int j = 0; j < 16; j++) {
            float p = S[i][j];
            float4 v0 = *(const float4*)&sV[j][d0];
            float4 v1 = *(const float4*)&sV[j][d0 + 4];
            acc0.x += p * v0.x; acc0.y += p * v0.y; acc0.z += p * v0.z; acc0.w += p * v0.w;
            acc1.x += p * v1.x; acc1.y += p * v1.y; acc1.z += p * v1.z; acc1.w += p * v1.w;
        }
        float inv = sinv[i];
        sO[i][d0 + 0] = acc0.x * inv; sO[i][d0 + 1] = acc0.y * inv;
        sO[i][d0 + 2] = acc0.z * inv; sO[i][d0 + 3] = acc0.w * inv;
        sO[i][d0 + 4] = acc1.x * inv; sO[i][d0 + 5] = acc1.y * inv;
        sO[i][d0 + 6] = acc1.z * inv; sO[i][d0 + 7] = acc1.w * inv;
    }
    __syncthreads();

    // LayerNorm stats per (i)
    if (tid < 16) {
        float mu = 0.f, m2 = 0.f;
        #pragma unroll 8
        for (int d = 0; d < 64; d++) {
            float x = sO[tid][d];
            mu += x;
            m2 += x * x;
        }
        mu *= (1.f / 64.f);
        m2 = m2 * (1.f / 64.f) - mu * mu;
        smu[tid] = mu;
        srstd[tid] = rsqrtf(m2 + 1e-5f);
    }
    __syncthreads();

    // masked pool over positions, write pooled[b,h,d]
    if (tid < 64) {
        int d = tid;
        float g = gamma[d], bt = beta[d];
        float acc = 0.f;
        int cnt = 0;
        #pragma unroll
        for (int i = 0; i < 16; i++) {
            if (code[i] != 0) {
                float y = (sO[i][d] - smu[i]) * srstd[i];
                acc += y * g + bt;
                cnt++;
            }
        }
        g_pooled[b * 512 + h * 64 + d] = acc / (float)cnt;
    }
}

// -------- K3: per-(b,d) MLP 8 -> relu16 -> 8  (grid 4096, block 128) --------
__global__ __launch_bounds__(128) void mlp_kernel(
    const float* __restrict__ W1, const float* __restrict__ b1,
    const float* __restrict__ W2, const float* __restrict__ b2) {
    __shared__ float sW1[128], sB1[16], sW2[128], sB2[8];
    int tid = threadIdx.x;
    if (tid < 128) { sW1[tid] = W1[tid]; sW2[tid] = W2[tid]; }
    if (tid < 16) sB1[tid] = b1[tid];
    if (tid < 8)  sB2[tid] = b2[tid];
    __syncthreads();
    int b = blockIdx.x * 2 + (tid >> 6);
    int d = tid & 63;
    float hv[8];
    #pragma unroll
    for (int h = 0; h < 8; h++) hv[h] = g_pooled[b * 512 + h * 64 + d];
    float t[16];
    #pragma unroll
    for (int u = 0; u < 16; u++) {
        float a = sB1[u];
        #pragma unroll
        for (int h = 0; h < 8; h++) a = fmaf(hv[h], sW1[h * 16 + u], a);
        t[u] = fmaxf(a, 0.f);
    }
    #pragma unroll
    for (int o = 0; o < 8; o++) {
        float a = sB2[o];
        #pragma unroll
        for (int u = 0; u < 16; u++) a = fmaf(t[u], sW2[u * 8 + o], a);
        g_xflat[b * 512 + d * 8 + o] = a;
    }
}

// -------- K4: word gather + segment mean (grid 2048, block 256) --------
__global__ void seg_kernel(const int* __restrict__ word_code,
                           const int* __restrict__ n_words,
                           float* __restrict__ out) {
    int n = blockIdx.x;
    int tid = threadIdx.x;
    int off = g_segoff[n];
    int cnt = n_words[n];
    float inv = 1.f / (float)cnt;
    for (int c = tid; c < 512; c += 256) {
        float a = 0.f;
        for (int w = 0; w < cnt; w++) {
            int wc = word_code[off + w];
            a += g_xflat[wc * 512 + c];
        }
        out[n * 512 + c] = a * inv;
    }
}

extern "C" void kernel_launch(void* const* d_in, const int* in_sizes, int n_in,
                              void* d_out, int out_size) {
    const float* char_emb = (const float*)d_in[0];
    const float* Wc       = (const float*)d_in[1];
    const float* bc       = (const float*)d_in[2];
    const float* Wp       = (const float*)d_in[3];
    const float* bp       = (const float*)d_in[4];
    const float* gamma    = (const float*)d_in[5];
    const float* beta     = (const float*)d_in[6];
    const float* W1       = (const float*)d_in[7];
    const float* b1       = (const float*)d_in[8];
    const float* W2       = (const float*)d_in[9];
    const float* b2       = (const float*)d_in[10];
    const int* char_code  = (const int*)d_in[11];
    const int* word_code  = (const int*)d_in[12];
    const int* n_words    = (const int*)d_in[13];
    float* out = (float*)d_out;

    qkv_pos_kernel<<<16, 256>>>(Wp, bp);
    qkv_char_kernel<<<256, 256>>>(char_emb, Wc, bc);
    seg_scan_kernel<<<1, 256>>>(n_words);
    attn_kernel<<<B_SZ * H_SZ, 128>>>(char_code, gamma, beta);
    mlp_kernel<<<B_SZ / 2, 128>>>(W1, b1, W2, b2);
    seg_kernel<<<N_NAMES, 256>>>(word_code, n_words, out);
}

// round 4
// speedup vs baseline: 1.1244x; 1.1244x over previous
#include <cuda_runtime.h>
#include <cuda_bf16.h>
#include <math.h>

#define V_SZ 2048
#define L_SZ 16
#define H_SZ 8
#define D_SZ 64
#define B_SZ 8192
#define NW_TOTAL 8192
#define N_NAMES 2048
#define TEMP_INV 0.125f
#define SMPAD 68

// -------- scratch --------
__device__ float g_cq[V_SZ * H_SZ * D_SZ];
__device__ float g_ck[V_SZ * H_SZ * D_SZ];
__device__ float g_cv[V_SZ * H_SZ * D_SZ];
__device__ float g_pq[L_SZ * H_SZ * D_SZ];
__device__ float g_pk[L_SZ * H_SZ * D_SZ];
__device__ float g_pv[L_SZ * H_SZ * D_SZ];
__device__ float g_qk[H_SZ * V_SZ * V_SZ];       // 134MB: char_qk[h][x][y]
__device__ float g_cp[H_SZ * V_SZ * L_SZ];       // cp[h][v][l]
__device__ float g_posqk[H_SZ * L_SZ * L_SZ];    // pos_qk[h][i][j]
__device__ float g_pooled[B_SZ * H_SZ * D_SZ];
__device__ float g_xflat[B_SZ * 512];
__device__ int   g_segoff[N_NAMES];

// -------- K0: pos embedding -> pq/pk/pv --------
__global__ void qkv_pos_kernel(const float* __restrict__ Wp, const float* __restrict__ bp) {
    int l = blockIdx.x;
    __shared__ float sp[64];
    int tid = threadIdx.x;
    if (tid < 64) {
        int f = tid & 31;
        double inv = pow(10000.0, -(double)f / 32.0);
        double ph = (double)l * inv;
        sp[tid] = (float)((tid < 32) ? cos(ph) : sin(ph));
    }
    __syncthreads();
    for (int c = tid; c < 1536; c += 256) {
        float a = 0.f;
        #pragma unroll 8
        for (int k = 0; k < 64; k++) a += sp[k] * Wp[k * 1536 + c];
        a += bp[c];
        int t = c >> 9, rem = c & 511;
        float* dst = (t == 0) ? g_pq : (t == 1) ? g_pk : g_pv;
        dst[l * 512 + rem] = a;
    }
}

// -------- K1: char_emb @ Wc + bc -> cq/ck/cv --------
__global__ __launch_bounds__(256) void qkv_char_kernel(
    const float* __restrict__ emb, const float* __restrict__ Wc, const float* __restrict__ bc) {
    int row0 = blockIdx.x * 8;
    __shared__ float se[8][64];
    int tid = threadIdx.x;
    for (int idx = tid; idx < 512; idx += 256)
        se[idx >> 6][idx & 63] = emb[(row0 + (idx >> 6)) * 64 + (idx & 63)];
    __syncthreads();
    float acc[6][8];
    #pragma unroll
    for (int c = 0; c < 6; c++)
        #pragma unroll
        for (int r = 0; r < 8; r++) acc[c][r] = 0.f;
    for (int k = 0; k < 64; k++) {
        float w[6];
        #pragma unroll
        for (int c = 0; c < 6; c++) w[c] = Wc[k * 1536 + tid + c * 256];
        #pragma unroll
        for (int r = 0; r < 8; r++) {
            float e = se[r][k];
            #pragma unroll
            for (int c = 0; c < 6; c++) acc[c][r] = fmaf(e, w[c], acc[c][r]);
        }
    }
    #pragma unroll
    for (int c = 0; c < 6; c++) {
        int col = tid + c * 256;
        float bias = bc[col];
        int t = col >> 9, rem = col & 511;
        float* dst = (t == 0) ? g_cq : (t == 1) ? g_ck : g_cv;
        #pragma unroll
        for (int r = 0; r < 8; r++) dst[(row0 + r) * 512 + rem] = acc[c][r] + bias;
    }
}

// -------- K2: char_qk GEMM: g_qk[h][x][y] = cq_x[h]·ck_y[h] --------
// grid (16,16,8); block 256; 128x128 tile, k-chunks of 32, k-major smem.
__global__ __launch_bounds__(256) void charqk_kernel() {
    __shared__ float sA[32][128];
    __shared__ float sB[32][128];
    int tid = threadIdx.x;
    int X0 = blockIdx.x * 128, Y0 = blockIdx.y * 128, h = blockIdx.z;
    int tx = tid & 15, ty = tid >> 4;
    int x0 = ty * 8, y0 = tx * 8;
    float acc[8][8];
    #pragma unroll
    for (int r = 0; r < 8; r++)
        #pragma unroll
        for (int c = 0; c < 8; c++) acc[r][c] = 0.f;

    int lx = tid & 127;           // row within tile
    int d0 = (tid >> 7) * 16;     // k-offset half

    for (int kc = 0; kc < 2; kc++) {
        int gk = h * 64 + kc * 32 + d0;
        #pragma unroll
        for (int i = 0; i < 4; i++) {
            float4 a4 = *(const float4*)&g_cq[(X0 + lx) * 512 + gk + i * 4];
            float4 b4 = *(const float4*)&g_ck[(Y0 + lx) * 512 + gk + i * 4];
            int kk = d0 + i * 4;
            sA[kk + 0][lx] = a4.x; sA[kk + 1][lx] = a4.y; sA[kk + 2][lx] = a4.z; sA[kk + 3][lx] = a4.w;
            sB[kk + 0][lx] = b4.x; sB[kk + 1][lx] = b4.y; sB[kk + 2][lx] = b4.z; sB[kk + 3][lx] = b4.w;
        }
        __syncthreads();
        #pragma unroll
        for (int k = 0; k < 32; k++) {
            float4 aA = *(const float4*)&sA[k][x0];
            float4 aB = *(const float4*)&sA[k][x0 + 4];
            float4 bA = *(const float4*)&sB[k][y0];
            float4 bB = *(const float4*)&sB[k][y0 + 4];
            float av[8] = {aA.x, aA.y, aA.z, aA.w, aB.x, aB.y, aB.z, aB.w};
            float bv[8] = {bA.x, bA.y, bA.z, bA.w, bB.x, bB.y, bB.z, bB.w};
            #pragma unroll
            for (int r = 0; r < 8; r++)
                #pragma unroll
                for (int c = 0; c < 8; c++) acc[r][c] = fmaf(av[r], bv[c], acc[r][c]);
        }
        __syncthreads();
    }
    #pragma unroll
    for (int r = 0; r < 8; r++) {
        float* dst = &g_qk[h * (V_SZ * V_SZ) + (X0 + x0 + r) * V_SZ + Y0 + y0];
        *(float4*)dst       = make_float4(acc[r][0], acc[r][1], acc[r][2], acc[r][3]);
        *(float4*)(dst + 4) = make_float4(acc[r][4], acc[r][5], acc[r][6], acc[r][7]);
    }
}

// -------- K3: cp[h][v][j] = cq_v·pk_j + pq_j·ck_v  (grid 2048, block 128) --------
__global__ __launch_bounds__(128) void cp_kernel() {
    int v = blockIdx.x;
    int tid = threadIdx.x;
    __shared__ float scq[512], sck[512];
    {
        float4 a = *(const float4*)&g_cq[v * 512 + tid * 4];
        float4 b = *(const float4*)&g_ck[v * 512 + tid * 4];
        *(float4*)&scq[tid * 4] = a;
        *(float4*)&sck[tid * 4] = b;
    }
    __syncthreads();
    int h = tid >> 4, j = tid & 15;
    float d1 = 0.f, d2 = 0.f;
    #pragma unroll
    for (int i = 0; i < 16; i++) {
        int d = i * 4;
        float4 pk4 = *(const float4*)&g_pk[j * 512 + h * 64 + d];
        float4 pq4 = *(const float4*)&g_pq[j * 512 + h * 64 + d];
        float4 cq4 = *(const float4*)&scq[h * 64 + d];
        float4 ck4 = *(const float4*)&sck[h * 64 + d];
        d1 += cq4.x * pk4.x + cq4.y * pk4.y + cq4.z * pk4.z + cq4.w * pk4.w;
        d2 += pq4.x * ck4.x + pq4.y * ck4.y + pq4.z * ck4.z + pq4.w * ck4.w;
    }
    g_cp[(h * V_SZ + v) * 16 + j] = d1 + d2;
}

// -------- K4: pos_qk[h][i][j] (1 block, 128 threads) --------
__global__ void posqk_kernel() {
    int t = threadIdx.x;  // (h,i)
    int h = t >> 4, i = t & 15;
    for (int j = 0; j < 16; j++) {
        float a = 0.f;
        #pragma unroll
        for (int d = 0; d < 64; d += 4) {
            float4 q4 = *(const float4*)&g_pq[i * 512 + h * 64 + d];
            float4 k4 = *(const float4*)&g_pk[j * 512 + h * 64 + d];
            a += q4.x * k4.x + q4.y * k4.y + q4.z * k4.z + q4.w * k4.w;
        }
        g_posqk[(h << 8) + (i << 4) + j] = a;
    }
}

// -------- K_scan --------
__global__ void seg_scan_kernel(const int* __restrict__ nw) {
    __shared__ int s[N_NAMES];
    __shared__ int csum[32];
    int tid = threadIdx.x;
    for (int i = tid; i < N_NAMES; i += 256) s[i] = nw[i];
    __syncthreads();
    if (tid < 32) {
        int a = 0;
        for (int k = 0; k < 64; k++) a += s[tid * 64 + k];
        int x = a;
        #pragma unroll
        for (int o = 1; o < 32; o <<= 1) {
            int y = __shfl_up_sync(0xffffffff, x, o);
            if (tid >= o) x += y;
        }
        csum[tid] = x - a;
    }
    __syncthreads();
    if (tid < 32) {
        int off = csum[tid];
        for (int k = 0; k < 64; k++) {
            g_segoff[tid * 64 + k] = off;
            off += s[tid * 64 + k];
        }
    }
}

// -------- K5: attention via table gather + AV + LN + pool. Block per (h,b). --------
__global__ __launch_bounds__(128) void attn_kernel(
    const int* __restrict__ code_g, const float* __restrict__ gamma, const float* __restrict__ beta) {
    __shared__ float sV[16][SMPAD], sO[16][SMPAD];
    __shared__ float S[16][17];
    __shared__ int code[16];
    __shared__ float sinv[16], smu[16], srstd[16];

    int tid = threadIdx.x;
    int b = blockIdx.x & (B_SZ - 1);
    int h = blockIdx.x >> 13;

    if (tid < 16) code[tid] = code_g[b * 16 + tid];
    __syncthreads();

    // V gather: 1024 floats as 256 float4 (2 per thread)
    #pragma unroll
    for (int e = tid; e < 256; e += 128) {
        int p = e >> 4, d = (e & 15) * 4;
        float4 cv4 = *(const float4*)&g_cv[code[p] * 512 + h * 64 + d];
        float4 pv4 = *(const float4*)&g_pv[p * 512 + h * 64 + d];
        float4 v;
        v.x = cv4.x + pv4.x; v.y = cv4.y + pv4.y; v.z = cv4.z + pv4.z; v.w = cv4.w + pv4.w;
        *(float4*)&sV[p][d] = v;
    }

    // Score gather: 256 entries, 2 per thread, 3 LDG each
    #pragma unroll
    for (int e = tid; e < 256; e += 128) {
        int i = e >> 4, j = e & 15;
        int cj = code[j];
        float val;
        if (cj == 0) {
            val = -1e9f;
        } else {
            int ci = code[i];
            val = (g_qk[(h << 22) + (ci << 11) + cj]
                 + g_cp[((h << 11) + ci) * 16 + j]
                 + g_posqk[(h << 8) + (i << 4) + j]) * TEMP_INV;
        }
        S[i][j] = val;
    }
    __syncthreads();

    // Softmax per row
    if (tid < 16) {
        float m = -1e30f;
        #pragma unroll
        for (int j = 0; j < 16; j++) m = fmaxf(m, S[tid][j]);
        float sum = 0.f;
        #pragma unroll
        for (int j = 0; j < 16; j++) {
            float e = expf(S[tid][j] - m);
            S[tid][j] = e;
            sum += e;
        }
        sinv[tid] = 1.f / sum;
    }
    __syncthreads();

    // out = P @ V
    {
        int i = tid >> 3;
        int d0 = (tid & 7) * 8;
        float4 acc0 = make_float4(0.f, 0.f, 0.f, 0.f);
        float4 acc1 = make_float4(0.f, 0.f, 0.f, 0.f);
        #pragma unroll
        for (int j = 0; j < 16; j++) {
            float p = S[i][j];
            float4 v0 = *(const float4*)&sV[j][d0];
            float4 v1 = *(const float4*)&sV[j][d0 + 4];
            acc0.x += p * v0.x; acc0.y += p * v0.y; acc0.z += p * v0.z; acc0.w += p * v0.w;
            acc1.x += p * v1.x; acc1.y += p * v1.y; acc1.z += p * v1.z; acc1.w += p * v1.w;
        }
        float inv = sinv[i];
        sO[i][d0 + 0] = acc0.x * inv; sO[i][d0 + 1] = acc0.y * inv;
        sO[i][d0 + 2] = acc0.z * inv; sO[i][d0 + 3] = acc0.w * inv;
        sO[i][d0 + 4] = acc1.x * inv; sO[i][d0 + 5] = acc1.y * inv;
        sO[i][d0 + 6] = acc1.z * inv; sO[i][d0 + 7] = acc1.w * inv;
    }
    __syncthreads();

    // LayerNorm stats
    if (tid < 16) {
        float mu = 0.f, m2 = 0.f;
        #pragma unroll 8
        for (int d = 0; d < 64; d++) {
            float x = sO[tid][d];
            mu += x;
            m2 += x * x;
        }
        mu *= (1.f / 64.f);
        m2 = m2 * (1.f / 64.f) - mu * mu;
        smu[tid] = mu;
        srstd[tid] = rsqrtf(m2 + 1e-5f);
    }
    __syncthreads();

    // masked pool
    if (tid < 64) {
        int d = tid;
        float g = gamma[d], bt = beta[d];
        float acc = 0.f;
        int cnt = 0;
        #pragma unroll
        for (int i = 0; i < 16; i++) {
            if (code[i] != 0) {
                float y = (sO[i][d] - smu[i]) * srstd[i];
                acc += y * g + bt;
                cnt++;
            }
        }
        g_pooled[b * 512 + h * 64 + d] = acc / (float)cnt;
    }
}

// -------- K6: MLP --------
__global__ __launch_bounds__(128) void mlp_kernel(
    const float* __restrict__ W1, const float* __restrict__ b1,
    const float* __restrict__ W2, const float* __restrict__ b2) {
    __shared__ float sW1[128], sB1[16], sW2[128], sB2[8];
    int tid = threadIdx.x;
    if (tid < 128) { sW1[tid] = W1[tid]; sW2[tid] = W2[tid]; }
    if (tid < 16) sB1[tid] = b1[tid];
    if (tid < 8)  sB2[tid] = b2[tid];
    __syncthreads();
    int b = blockIdx.x * 2 + (tid >> 6);
    int d = tid & 63;
    float hv[8];
    #pragma unroll
    for (int h = 0; h < 8; h++) hv[h] = g_pooled[b * 512 + h * 64 + d];
    float t[16];
    #pragma unroll
    for (int u = 0; u < 16; u++) {
        float a = sB1[u];
        #pragma unroll
        for (int h = 0; h < 8; h++) a = fmaf(hv[h], sW1[h * 16 + u], a);
        t[u] = fmaxf(a, 0.f);
    }
    #pragma unroll
    for (int o = 0; o < 8; o++) {
        float a = sB2[o];
        #pragma unroll
        for (int u = 0; u < 16; u++) a = fmaf(t[u], sW2[u * 8 + o], a);
        g_xflat[b * 512 + d * 8 + o] = a;
    }
}

// -------- K7: word gather + segment mean --------
__global__ void seg_kernel(const int* __restrict__ word_code,
                           const int* __restrict__ n_words,
                           float* __restrict__ out) {
    int n = blockIdx.x;
    int tid = threadIdx.x;
    int off = g_segoff[n];
    int cnt = n_words[n];
    float inv = 1.f / (float)cnt;
    for (int c = tid; c < 512; c += 256) {
        float a = 0.f;
        for (int w = 0; w < cnt; w++) {
            int wc = word_code[off + w];
            a += g_xflat[wc * 512 + c];
        }
        out[n * 512 + c] = a * inv;
    }
}

extern "C" void kernel_launch(void* const* d_in, const int* in_sizes, int n_in,
                              void* d_out, int out_size) {
    const float* char_emb = (const float*)d_in[0];
    const float* Wc       = (const float*)d_in[1];
    const float* bc       = (const float*)d_in[2];
    const float* Wp       = (const float*)d_in[3];
    const float* bp       = (const float*)d_in[4];
    const float* gamma    = (const float*)d_in[5];
    const float* beta     = (const float*)d_in[6];
    const float* W1       = (const float*)d_in[7];
    const float* b1       = (const float*)d_in[8];
    const float* W2       = (const float*)d_in[9];
    const float* b2       = (const float*)d_in[10];
    const int* char_code  = (const int*)d_in[11];
    const int* word_code  = (const int*)d_in[12];
    const int* n_words    = (const int*)d_in[13];
    float* out = (float*)d_out;

    qkv_pos_kernel<<<16, 256>>>(Wp, bp);
    qkv_char_kernel<<<256, 256>>>(char_emb, Wc, bc);
    posqk_kernel<<<1, 128>>>();
    cp_kernel<<<V_SZ, 128>>>();
    charqk_kernel<<<dim3(16, 16, 8), 256>>>();
    seg_scan_kernel<<<1, 256>>>(n_words);
    attn_kernel<<<B_SZ * H_SZ, 128>>>(char_code, gamma, beta);
    mlp_kernel<<<B_SZ / 2, 128>>>(W1, b1, W2, b2);
    seg_kernel<<<N_NAMES, 256>>>(word_code, n_words, out);
}